// round 3
// baseline (speedup 1.0000x reference)
#include <cuda_runtime.h>
#include <cstdint>

// ---------------------------------------------------------------------------
// Problem constants
//   SHAPE = (4, 8, 8, 4), I_CH=32, O_CH=128, BATCH=64, RANK=32
//   core0: (32, 64, 1, 4, 32)   strides (floats): i 8192, b 128, m 32, j 1
//   core1: (32, 64, 32, 8, 32)  strides: i 524288, b 8192, k 256, m 32, j 1
//   core2: same as core1
//   core3: (32, 64, 32, 4, 1)   strides: i 8192, b 128, k 4, m 1
//   weight:(32, 24, 128)        strides: i 3072, row 128, o 1
// Outputs concatenated flat:
//   y0: (128,64,1,4,32)  = 1,048,576
//   y1: (128,64,32,8,32) = 67,108,864
//   y2: same
//   y3: (128,64,32,4,1)  = 1,048,576
// ---------------------------------------------------------------------------

static const size_t Y0_OFF = 0;
static const size_t Y1_OFF = 1048576;
static const size_t Y2_OFF = 1048576 + 67108864ull;
static const size_t Y3_OFF = 1048576 + 2ull * 67108864ull;

// ---------------------------------------------------------------------------
// y0: out0[o,b,m,j] = sum_i W[i, m, o] * core0[i,b,0,m,j]
// grid 256 = (b*4 + m), 256 threads
// ---------------------------------------------------------------------------
__global__ void __launch_bounds__(256) y0_kernel(
    const float* __restrict__ core0, const float* __restrict__ weight,
    float* __restrict__ out)
{
    __shared__ float cs[32 * 32];     // [i][j]
    __shared__ float Ws[32 * 128];    // [i][o]
    const int bm = blockIdx.x;
    const int b = bm >> 2;
    const int m = bm & 3;
    const int tid = threadIdx.x;

    {   // load core slice (1024 floats, 256 float4)
        int i = tid >> 3, j4 = tid & 7;
        float4 v = *reinterpret_cast<const float4*>(
            core0 + (size_t)i * 8192 + b * 128 + m * 32 + j4 * 4);
        *reinterpret_cast<float4*>(&cs[i * 32 + j4 * 4]) = v;
    }
    #pragma unroll
    for (int q = 0; q < 4; ++q) {     // load W slice (4096 floats, 1024 float4)
        int idx = tid + 256 * q;
        int i = idx >> 5, o4 = idx & 31;
        float4 v = *reinterpret_cast<const float4*>(
            weight + (size_t)i * 3072 + m * 128 + o4 * 4);
        *reinterpret_cast<float4*>(&Ws[i * 128 + o4 * 4]) = v;
    }
    __syncthreads();

    const int j = tid & 31;
    const int obase = (tid >> 5) * 16;
    float acc[16];
    #pragma unroll
    for (int t = 0; t < 16; ++t) acc[t] = 0.f;
    #pragma unroll 4
    for (int i = 0; i < 32; ++i) {
        float v = cs[i * 32 + j];
        #pragma unroll
        for (int oo = 0; oo < 16; ++oo)
            acc[oo] = fmaf(Ws[i * 128 + obase + oo], v, acc[oo]);
    }
    #pragma unroll
    for (int oo = 0; oo < 16; ++oo)
        out[(size_t)(obase + oo) * 8192 + b * 128 + m * 32 + j] = acc[oo];
}

// ---------------------------------------------------------------------------
// y3: out3[o,b,k,m] = sum_i W[i, 20+m, o] * core3[i,b,k,m]
// grid 256 = (oq*64 + b), 256 threads ; km = k*4+m flattened (contiguous)
// ---------------------------------------------------------------------------
__global__ void __launch_bounds__(256) y3_kernel(
    const float* __restrict__ core3, const float* __restrict__ weight,
    float* __restrict__ out)
{
    __shared__ float cs[32 * 128];    // [i][km]
    __shared__ float Ws[32 * 32 * 4]; // [i][o_local][mm]
    const int b = blockIdx.x & 63;
    const int oq = blockIdx.x >> 6;
    const int tid = threadIdx.x;

    #pragma unroll
    for (int q = 0; q < 4; ++q) {     // 4096 floats as 1024 float4
        int idx = tid + 256 * q;
        int i = idx >> 5, km4 = idx & 31;
        float4 v = *reinterpret_cast<const float4*>(
            core3 + (size_t)i * 8192 + b * 128 + km4 * 4);
        *reinterpret_cast<float4*>(&cs[i * 128 + km4 * 4]) = v;
    }
    #pragma unroll
    for (int q = 0; q < 16; ++q) {    // W slice, transposed store [i][ol][mm]
        int idx = tid + 256 * q;      // 0..4095
        int i = idx >> 7;
        int rem = idx & 127;
        int mm = rem >> 5;
        int ol = rem & 31;
        Ws[(i * 32 + ol) * 4 + mm] =
            weight[(size_t)i * 3072 + (20 + mm) * 128 + oq * 32 + ol];
    }
    __syncthreads();

    const int km = tid & 127;
    const int oh = tid >> 7;          // 0..1
    const int mm = km & 3;
    float acc[16];
    #pragma unroll
    for (int t = 0; t < 16; ++t) acc[t] = 0.f;
    #pragma unroll 4
    for (int i = 0; i < 32; ++i) {
        float v = cs[i * 128 + km];
        #pragma unroll
        for (int oo = 0; oo < 16; ++oo)
            acc[oo] = fmaf(Ws[(i * 32 + oh * 16 + oo) * 4 + mm], v, acc[oo]);
    }
    #pragma unroll
    for (int oo = 0; oo < 16; ++oo) {
        int o = oq * 32 + oh * 16 + oo;
        out[((size_t)o * 64 + b) * 128 + km] = acc[oo];
    }
}

// ---------------------------------------------------------------------------
// Main fused kernel for cores 1 & 2:
//   A[o,k,j] = sum_i 0.5*W[i,off+m,o] * (c[i,b,j,m,k] - c[i,b,k,m,j])   (skew)
//   Q = (I-A)^{-1}(I+A) = 2*(I-A)^{-1} - I
// Grid: (og=8, b*8+m=512, core=2), 512 threads.
// Phase 1: stage core slice in smem (i-chunks of 8), 496 threads accumulate
//          upper-triangle of 16 A-matrices in registers, mirror into smem.
// Phase 2: one warp per matrix, row-per-lane register Gauss-Jordan inverse
//          (no pivoting needed: sym(I-A)=I => all pivots >= 1, stable).
// ---------------------------------------------------------------------------
__global__ void __launch_bounds__(512) cayley_kernel(
    const float* __restrict__ core1,
    const float* __restrict__ core2,
    const float* __restrict__ weight,
    float* __restrict__ out)
{
    const int og = blockIdx.x;            // 0..7   (o-group of 16)
    const int bm = blockIdx.y;            // 0..511
    const int b  = bm >> 3;
    const int m  = bm & 7;
    const int c  = blockIdx.z;            // 0..1
    const float* core = c ? core2 : core1;
    float* yout = out + (c ? Y2_OFF : Y1_OFF);
    const int woff = 4 + 8 * c;           // weight row offset for this core

    extern __shared__ float smem[];
    float* raw  = smem;                   // [8][32][33]  = 8448 floats
    float* Amat = smem + 8448;            // [16][32][33] = 16896 floats
    float* Ws   = smem + 8448 + 16896;    // [32][16]     = 512 floats

    const int tid = threadIdx.x;

    // --- load 0.5*W slice: Ws[i][oo], one value per thread -----------------
    {
        int i  = tid >> 4;
        int oo = tid & 15;
        Ws[i * 16 + oo] =
            0.5f * weight[(size_t)i * 3072 + (woff + m) * 128 + og * 16 + oo];
    }

    // --- map thread -> strict-upper-triangle pair (pk < pj) ----------------
    int pk = 0, pj = 0;
    if (tid < 496) {
        int rem = tid, k = 0;
        #pragma unroll 1
        while (rem >= 31 - k) { rem -= 31 - k; ++k; }
        pk = k;
        pj = k + 1 + rem;
    }

    float acc[16];
    #pragma unroll
    for (int oo = 0; oo < 16; ++oo) acc[oo] = 0.f;

    const float* cbase = core + (size_t)b * 8192 + m * 32;

    // --- phase 1: accumulate A upper triangle over i in chunks of 8 --------
    for (int ch = 0; ch < 4; ++ch) {
        __syncthreads();
        #pragma unroll
        for (int q = 0; q < 4; ++q) {     // 2048 float4 per chunk, 4/thread
            int idx = tid + 512 * q;
            int il  = idx >> 8;           // 0..7
            int rem = idx & 255;
            int k   = rem >> 3;           // 0..31
            int j4  = rem & 7;            // 0..7
            const float4 v = *reinterpret_cast<const float4*>(
                cbase + (size_t)(ch * 8 + il) * 524288 + k * 256 + j4 * 4);
            float* d = &raw[(il * 32 + k) * 33 + j4 * 4];
            d[0] = v.x; d[1] = v.y; d[2] = v.z; d[3] = v.w;
        }
        __syncthreads();
        if (tid < 496) {
            #pragma unroll
            for (int il = 0; il < 8; ++il) {
                float dval = raw[(il * 32 + pj) * 33 + pk]
                           - raw[(il * 32 + pk) * 33 + pj];
                const float* wrow = &Ws[(ch * 8 + il) * 16];
                #pragma unroll
                for (int oo = 0; oo < 16; ++oo)
                    acc[oo] = fmaf(wrow[oo], dval, acc[oo]);
            }
        }
    }

    // --- mirror into smem A matrices (padded rows of 33) -------------------
    if (tid < 496) {
        #pragma unroll
        for (int oo = 0; oo < 16; ++oo) {
            Amat[(oo * 32 + pk) * 33 + pj] = acc[oo];
            Amat[(oo * 32 + pj) * 33 + pk] = -acc[oo];
        }
    } else {
        int oo = tid - 496;               // 0..15 : zero the diagonal
        #pragma unroll
        for (int dd = 0; dd < 32; ++dd)
            Amat[(oo * 32 + dd) * 33 + dd] = 0.f;
    }
    __syncthreads();

    // --- phase 2: per-warp register Gauss-Jordan inverse of M = I - A ------
    const int w    = tid >> 5;            // warp -> matrix index oo
    const int lane = tid & 31;            // lane -> row index

    float M[32];
    #pragma unroll
    for (int q = 0; q < 32; ++q)
        M[q] = (lane == q ? 1.0f : 0.0f) - Amat[(w * 32 + lane) * 33 + q];

    #pragma unroll
    for (int p = 0; p < 32; ++p) {
        float piv = __shfl_sync(0xffffffffu, M[p], p);
        float d   = __fdividef(1.0f, piv);        // pivots >= 1, always safe
        // lane==p scales its own row by d via g = 1-d (since pr[q]==M[q] there)
        float g   = (lane == p) ? (1.0f - d) : M[p] * d;
        #pragma unroll
        for (int q = 0; q < 32; ++q) {
            if (q == p) continue;
            float prq = __shfl_sync(0xffffffffu, M[q], p);
            M[q] = fmaf(-g, prq, M[q]);
        }
        M[p] = (lane == p) ? d : -g;
    }

    // --- Q = 2*Minv - I ; write row 'lane' of matrix (o, b, m) -------------
    const int o = og * 16 + w;
    float* dst = yout + ((size_t)o * 64 + b) * 8192 + lane * 256 + m * 32;
    #pragma unroll
    for (int qq = 0; qq < 8; ++qq) {
        float4 v;
        v.x = 2.f * M[qq * 4 + 0] - (lane == qq * 4 + 0 ? 1.f : 0.f);
        v.y = 2.f * M[qq * 4 + 1] - (lane == qq * 4 + 1 ? 1.f : 0.f);
        v.z = 2.f * M[qq * 4 + 2] - (lane == qq * 4 + 2 ? 1.f : 0.f);
        v.w = 2.f * M[qq * 4 + 3] - (lane == qq * 4 + 3 ? 1.f : 0.f);
        *reinterpret_cast<float4*>(dst + qq * 4) = v;
    }
}

// ---------------------------------------------------------------------------
extern "C" void kernel_launch(void* const* d_in, const int* in_sizes, int n_in,
                              void* d_out, int out_size)
{
    (void)in_sizes; (void)n_in; (void)out_size;
    const float* core0  = (const float*)d_in[0];
    const float* core1  = (const float*)d_in[1];
    const float* core2  = (const float*)d_in[2];
    const float* core3  = (const float*)d_in[3];
    const float* weight = (const float*)d_in[4];
    float* out = (float*)d_out;

    static const int SMEM_BYTES = (8448 + 16896 + 512) * 4;   // 103424 B
    cudaFuncSetAttribute(cayley_kernel,
                         cudaFuncAttributeMaxDynamicSharedMemorySize,
                         SMEM_BYTES);

    y0_kernel<<<256, 256>>>(core0, weight, out + Y0_OFF);
    y3_kernel<<<256, 256>>>(core3, weight, out + Y3_OFF);
    cayley_kernel<<<dim3(8, 512, 2), 512, SMEM_BYTES>>>(core1, core2, weight, out);
}